// round 1
// baseline (speedup 1.0000x reference)
#include <cuda_runtime.h>
#include <math.h>

#define SEQ    1024
#define DIM    1024
#define NH     16
#define HD     64
#define LAYERS 6
#define BATCH  2
#define ROWS   (BATCH*SEQ)   // 2048
#define FFD    (4*DIM)       // 4096
#define VOCAB  32000

// ---- scratch (device globals: allocation-free) ----
__device__ float g_x  [ROWS*DIM];
__device__ float g_qkv[ROWS*3*DIM];
__device__ float g_ao [ROWS*DIM];
__device__ float g_ff [ROWS*FFD];
__device__ float g_t  [ROWS*DIM];

// =================== embedding ===================
__global__ void embed_kernel(const int* __restrict__ X, const float* __restrict__ tok,
                             const float* __restrict__ pos, float* __restrict__ x) {
    int row = blockIdx.x;            // 0..2047
    int s   = row % SEQ;
    int v   = X[row];
    const float* te = tok + (size_t)v * DIM;
    const float* pe = pos + (size_t)s * DIM;
    float* xr = x + (size_t)row * DIM;
    for (int d = threadIdx.x; d < DIM; d += blockDim.x)
        xr[d] = te[d] + pe[d];
}

// =================== GEMM: C[M,N] = A[M,K] @ B[K,N] + bias, EPI 1 = exact GELU ===================
// BM=128, BN=64, BK=16, 256 threads, 8x4 per thread, register prefetch.
__device__ __forceinline__ float gelu_exact(float v) {
    return 0.5f * v * (1.0f + erff(v * 0.70710678118654752f));
}

template<int EPI>
__global__ __launch_bounds__(256) void gemm_kernel(
    const float* __restrict__ A, const float* __restrict__ B,
    const float* __restrict__ bias, float* __restrict__ C,
    int N, int K) {
    __shared__ float As[16][132];
    __shared__ float Bs[16][64];
    const int t  = threadIdx.x;
    const int bm = blockIdx.y * 128;
    const int bn = blockIdx.x * 64;
    const int ty = t >> 4, tx = t & 15;

    const float* Ab = A + (size_t)bm * K;
    const float* Bb = B + bn;

    float4 ra0, ra1, rb;
    const int am0 = (t      ) >> 2, ak0 = ((t      ) & 3) << 2;
    const int am1 = (t + 256) >> 2, ak1 = ((t + 256) & 3) << 2;
    const int bk  = t >> 4,        bnq = (t & 15) << 2;

    float acc[8][4];
    #pragma unroll
    for (int i = 0; i < 8; i++)
        #pragma unroll
        for (int j = 0; j < 4; j++) acc[i][j] = 0.f;

    // prologue fetch + store
    ra0 = *(const float4*)(Ab + (size_t)am0 * K + ak0);
    ra1 = *(const float4*)(Ab + (size_t)am1 * K + ak1);
    rb  = *(const float4*)(Bb + (size_t)bk  * N + bnq);
    As[ak0+0][am0]=ra0.x; As[ak0+1][am0]=ra0.y; As[ak0+2][am0]=ra0.z; As[ak0+3][am0]=ra0.w;
    As[ak1+0][am1]=ra1.x; As[ak1+1][am1]=ra1.y; As[ak1+2][am1]=ra1.z; As[ak1+3][am1]=ra1.w;
    *(float4*)(&Bs[bk][bnq]) = rb;
    __syncthreads();

    for (int k0 = 16; k0 <= K; k0 += 16) {
        if (k0 < K) {   // prefetch next tile into registers
            ra0 = *(const float4*)(Ab + (size_t)am0 * K + k0 + ak0);
            ra1 = *(const float4*)(Ab + (size_t)am1 * K + k0 + ak1);
            rb  = *(const float4*)(Bb + (size_t)(k0 + bk) * N + bnq);
        }
        #pragma unroll
        for (int k = 0; k < 16; k++) {
            float4 a0 = *(const float4*)(&As[k][ty*8]);
            float4 a1 = *(const float4*)(&As[k][ty*8+4]);
            float4 bv = *(const float4*)(&Bs[k][tx*4]);
            float a[8] = {a0.x,a0.y,a0.z,a0.w,a1.x,a1.y,a1.z,a1.w};
            float b[4] = {bv.x,bv.y,bv.z,bv.w};
            #pragma unroll
            for (int i = 0; i < 8; i++)
                #pragma unroll
                for (int j = 0; j < 4; j++)
                    acc[i][j] += a[i] * b[j];
        }
        __syncthreads();
        if (k0 < K) {
            As[ak0+0][am0]=ra0.x; As[ak0+1][am0]=ra0.y; As[ak0+2][am0]=ra0.z; As[ak0+3][am0]=ra0.w;
            As[ak1+0][am1]=ra1.x; As[ak1+1][am1]=ra1.y; As[ak1+2][am1]=ra1.z; As[ak1+3][am1]=ra1.w;
            *(float4*)(&Bs[bk][bnq]) = rb;
            __syncthreads();
        }
    }

    // epilogue
    const int n = bn + tx*4;
    float4 bv = *(const float4*)(bias + n);
    #pragma unroll
    for (int i = 0; i < 8; i++) {
        int m = bm + ty*8 + i;
        float4 o;
        o.x = acc[i][0] + bv.x; o.y = acc[i][1] + bv.y;
        o.z = acc[i][2] + bv.z; o.w = acc[i][3] + bv.w;
        if (EPI == 1) { o.x=gelu_exact(o.x); o.y=gelu_exact(o.y); o.z=gelu_exact(o.z); o.w=gelu_exact(o.w); }
        *(float4*)(C + (size_t)m * N + n) = o;
    }
}

// =================== fused causal attention (flash-style) ===================
// block = (qt, h, b); 256 threads; 64-row Q tile, 64-row K/V tiles, online softmax.
// thread (qi = t>>2, g = t&3): score cols kj = j*4+g, output cols dc = c*4+g.
#define ATTN_SMEM (4*64*65*4)

__global__ __launch_bounds__(256) void attn_kernel(const float* __restrict__ qkv,
                                                   float* __restrict__ out) {
    extern __shared__ float sm[];
    float (*Qs)[65] = (float(*)[65])(sm);
    float (*Ks)[65] = (float(*)[65])(sm + 64*65);
    float (*Vs)[65] = (float(*)[65])(sm + 2*64*65);
    float (*Ps)[65] = (float(*)[65])(sm + 3*64*65);
    const int qt = blockIdx.x, h = blockIdx.y, b = blockIdx.z;
    const int t  = threadIdx.x;
    const int qi = t >> 2, g = t & 3;

    const int RS = 3*DIM;
    const float* qbase = qkv + (size_t)(b*SEQ) * RS + h * (3*HD);

    // load Q tile (64x64)
    #pragma unroll
    for (int i = 0; i < 4; i++) {
        int f = t + i*256;
        int r = f >> 4;
        int c = (f & 15) << 2;
        float4 v = *(const float4*)(qbase + (size_t)(qt*64 + r) * RS + c);
        Qs[r][c]=v.x; Qs[r][c+1]=v.y; Qs[r][c+2]=v.z; Qs[r][c+3]=v.w;
    }

    float m = -INFINITY, l = 0.f;
    float o[16];
    #pragma unroll
    for (int i = 0; i < 16; i++) o[i] = 0.f;
    const int qg = qt*64 + qi;

    for (int kt = 0; kt <= qt; kt++) {
        __syncthreads();
        // load K,V tiles
        #pragma unroll
        for (int i = 0; i < 4; i++) {
            int f = t + i*256;
            int r = f >> 4;
            int c = (f & 15) << 2;
            const float* base = qbase + (size_t)(kt*64 + r) * RS + 64 + c;
            float4 kv = *(const float4*)(base);
            Ks[r][c]=kv.x; Ks[r][c+1]=kv.y; Ks[r][c+2]=kv.z; Ks[r][c+3]=kv.w;
            float4 vv = *(const float4*)(base + 64);
            Vs[r][c]=vv.x; Vs[r][c+1]=vv.y; Vs[r][c+2]=vv.z; Vs[r][c+3]=vv.w;
        }
        __syncthreads();

        // scores
        float sreg[16];
        #pragma unroll
        for (int j = 0; j < 16; j++) sreg[j] = 0.f;
        #pragma unroll
        for (int d0 = 0; d0 < 64; d0 += 16) {
            float q[16];
            #pragma unroll
            for (int dd = 0; dd < 16; dd++) q[dd] = Qs[qi][d0+dd];
            #pragma unroll
            for (int j = 0; j < 16; j++) {
                const float* kr = &Ks[j*4 + g][d0];
                #pragma unroll
                for (int dd = 0; dd < 16; dd++) sreg[j] += q[dd] * kr[dd];
            }
        }
        // scale + causal mask + tile max
        float tmax = -INFINITY;
        #pragma unroll
        for (int j = 0; j < 16; j++) {
            int kgl = kt*64 + j*4 + g;
            float sv = sreg[j] * 0.125f;
            if (kgl > qg) sv = -INFINITY;
            sreg[j] = sv;
            tmax = fmaxf(tmax, sv);
        }
        tmax = fmaxf(tmax, __shfl_xor_sync(0xffffffffu, tmax, 1));
        tmax = fmaxf(tmax, __shfl_xor_sync(0xffffffffu, tmax, 2));
        float nm   = fmaxf(m, tmax);
        float corr = expf(m - nm);   // m==-inf on first tile -> 0
        m = nm;

        float lsum = 0.f;
        #pragma unroll
        for (int j = 0; j < 16; j++) {
            float p = expf(sreg[j] - m);
            lsum += p;
            Ps[qi][j*4 + g] = p;
        }
        lsum += __shfl_xor_sync(0xffffffffu, lsum, 1);
        lsum += __shfl_xor_sync(0xffffffffu, lsum, 2);
        l = l * corr + lsum;
        #pragma unroll
        for (int c = 0; c < 16; c++) o[c] *= corr;
        __syncwarp();   // Ps rows are warp-local (qi*4+g all in same warp)

        // PV accumulate
        for (int kj = 0; kj < 64; kj++) {
            float p = Ps[qi][kj];
            const float* vr = &Vs[kj][0];
            #pragma unroll
            for (int c = 0; c < 16; c++)
                o[c] += p * vr[c*4 + g];
        }
    }

    float inv = 1.f / l;
    float* orow = out + (size_t)(b*SEQ + qg) * DIM + h * HD;
    #pragma unroll
    for (int c = 0; c < 16; c++)
        orow[c*4 + g] = o[c] * inv;
}

// =================== residual add + LayerNorm ===================
__global__ __launch_bounds__(256) void add_ln_kernel(
    const float* __restrict__ x, const float* __restrict__ a,
    const float* __restrict__ scale, const float* __restrict__ bias,
    float* __restrict__ out, int has_a) {
    int row = blockIdx.x;
    const float* xr = x + (size_t)row * DIM;
    const float* ar = a + (size_t)row * DIM;
    int t = threadIdx.x;
    float v[4];
    float s = 0.f, s2 = 0.f;
    #pragma unroll
    for (int i = 0; i < 4; i++) {
        int d = t + i*256;
        float val = xr[d] + (has_a ? ar[d] : 0.f);
        v[i] = val; s += val; s2 += val*val;
    }
    __shared__ float red[2][8];
    #pragma unroll
    for (int off = 16; off; off >>= 1) {
        s  += __shfl_xor_sync(0xffffffffu, s,  off);
        s2 += __shfl_xor_sync(0xffffffffu, s2, off);
    }
    if ((t & 31) == 0) { red[0][t>>5] = s; red[1][t>>5] = s2; }
    __syncthreads();
    float ts = 0.f, ts2 = 0.f;
    #pragma unroll
    for (int i = 0; i < 8; i++) { ts += red[0][i]; ts2 += red[1][i]; }
    float mean = ts * (1.0f/DIM);
    float var  = ts2 * (1.0f/DIM) - mean*mean;
    float inv  = rsqrtf(var + 1e-5f);
    float* orow = out + (size_t)row * DIM;
    #pragma unroll
    for (int i = 0; i < 4; i++) {
        int d = t + i*256;
        orow[d] = (v[i] - mean) * inv * scale[d] + bias[d];
    }
}

// =================== final row softmax over VOCAB (in place) ===================
__global__ __launch_bounds__(256) void softmax_kernel(float* __restrict__ out) {
    int row = blockIdx.x;
    float* r = out + (size_t)row * VOCAB;
    int t = threadIdx.x;
    float mx = -INFINITY;
    for (int i = t; i < VOCAB; i += 256) mx = fmaxf(mx, r[i]);
    __shared__ float redm[8], reds[8];
    #pragma unroll
    for (int off = 16; off; off >>= 1) mx = fmaxf(mx, __shfl_xor_sync(0xffffffffu, mx, off));
    if ((t & 31) == 0) redm[t>>5] = mx;
    __syncthreads();
    float bm = -INFINITY;
    #pragma unroll
    for (int i = 0; i < 8; i++) bm = fmaxf(bm, redm[i]);
    float sum = 0.f;
    for (int i = t; i < VOCAB; i += 256) {
        float e = expf(r[i] - bm);
        r[i] = e; sum += e;
    }
    #pragma unroll
    for (int off = 16; off; off >>= 1) sum += __shfl_xor_sync(0xffffffffu, sum, off);
    if ((t & 31) == 0) reds[t>>5] = sum;
    __syncthreads();
    float bs = 0.f;
    #pragma unroll
    for (int i = 0; i < 8; i++) bs += reds[i];
    float inv = 1.f / bs;
    for (int i = t; i < VOCAB; i += 256) r[i] *= inv;
}

// =================== launch ===================
extern "C" void kernel_launch(void* const* d_in, const int* in_sizes, int n_in,
                              void* d_out, int out_size) {
    const int*   X      = (const int*)  d_in[0];
    const float* tok    = (const float*)d_in[1];
    const float* pos    = (const float*)d_in[2];
    const float* qkv_w  = (const float*)d_in[3];
    const float* qkv_b  = (const float*)d_in[4];
    const float* out_w  = (const float*)d_in[5];
    const float* out_b  = (const float*)d_in[6];
    const float* ln1_s  = (const float*)d_in[7];
    const float* ln1_b  = (const float*)d_in[8];
    const float* ln2_s  = (const float*)d_in[9];
    const float* ln2_b  = (const float*)d_in[10];
    const float* ff1_w  = (const float*)d_in[11];
    const float* ff1_b  = (const float*)d_in[12];
    const float* ff2_w  = (const float*)d_in[13];
    const float* ff2_b  = (const float*)d_in[14];
    const float* lnf_s  = (const float*)d_in[15];
    const float* lnf_b  = (const float*)d_in[16];
    const float* head_w = (const float*)d_in[17];
    const float* head_b = (const float*)d_in[18];
    float* outp = (float*)d_out;

    float *x, *qkvb, *ao, *ff, *tmp;
    cudaGetSymbolAddress((void**)&x,    g_x);
    cudaGetSymbolAddress((void**)&qkvb, g_qkv);
    cudaGetSymbolAddress((void**)&ao,   g_ao);
    cudaGetSymbolAddress((void**)&ff,   g_ff);
    cudaGetSymbolAddress((void**)&tmp,  g_t);

    cudaFuncSetAttribute(attn_kernel, cudaFuncAttributeMaxDynamicSharedMemorySize, ATTN_SMEM);

    embed_kernel<<<ROWS, 256>>>(X, tok, pos, x);

    for (int l = 0; l < LAYERS; l++) {
        gemm_kernel<0><<<dim3(3*DIM/64, ROWS/128), 256>>>(x, qkv_w, qkv_b, qkvb, 3*DIM, DIM);
        attn_kernel<<<dim3(SEQ/64, NH, BATCH), 256, ATTN_SMEM>>>(qkvb, ao);
        gemm_kernel<0><<<dim3(DIM/64, ROWS/128), 256>>>(ao, out_w, out_b, tmp, DIM, DIM);
        add_ln_kernel<<<ROWS, 256>>>(x, tmp, ln1_s, ln1_b, x, 1);
        gemm_kernel<1><<<dim3(FFD/64, ROWS/128), 256>>>(x, ff1_w, ff1_b, ff, FFD, DIM);
        gemm_kernel<0><<<dim3(DIM/64, ROWS/128), 256>>>(ff, ff2_w, ff2_b, tmp, DIM, FFD);
        add_ln_kernel<<<ROWS, 256>>>(x, tmp, ln2_s, ln2_b, x, 1);
    }
    add_ln_kernel<<<ROWS, 256>>>(x, x, lnf_s, lnf_b, x, 0);
    gemm_kernel<0><<<dim3(VOCAB/64, ROWS/128), 256>>>(x, head_w, head_b, outp, VOCAB, DIM);
    softmax_kernel<<<ROWS, 256>>>(outp);
}

// round 2
// speedup vs baseline: 1.8157x; 1.8157x over previous
#include <cuda_runtime.h>
#include <math.h>
#include <stdint.h>

#define SEQ    1024
#define DIM    1024
#define NH     16
#define HD     64
#define LAYERS 6
#define BATCH  2
#define ROWS   (BATCH*SEQ)   // 2048
#define FFD    (4*DIM)       // 4096
#define VOCAB  32000

// ---- scratch (device globals: allocation-free) ----
__device__ float g_x  [ROWS*DIM];
__device__ float g_qkv[ROWS*3*DIM];
__device__ float g_ao [ROWS*DIM];
__device__ float g_ff [ROWS*FFD];
__device__ float g_t  [ROWS*DIM];

// =================== embedding ===================
__global__ void embed_kernel(const int* __restrict__ X, const float* __restrict__ tok,
                             const float* __restrict__ pos, float* __restrict__ x) {
    int row = blockIdx.x;
    int s   = row % SEQ;
    int v   = X[row];
    const float* te = tok + (size_t)v * DIM;
    const float* pe = pos + (size_t)s * DIM;
    float* xr = x + (size_t)row * DIM;
    for (int d = threadIdx.x; d < DIM; d += blockDim.x)
        xr[d] = te[d] + pe[d];
}

// =================== tf32 tensor-core GEMM ===================
// C[M,N] = A[M,K] @ B[K,N] + bias, optional exact-GELU epilogue.
// BM=128, BN=128, BK=16. 256 threads = 8 warps (2x4). Warp tile 64x32.
// mma.sync.aligned.m16n8k8.row.col.f32.tf32.tf32.f32, fp32 accumulate.
__device__ __forceinline__ float gelu_exact(float v) {
    return 0.5f * v * (1.0f + erff(v * 0.70710678118654752f));
}
__device__ __forceinline__ uint32_t tf32cvt(float f) {
    uint32_t u; asm("cvt.rna.tf32.f32 %0, %1;" : "=r"(u) : "f"(f)); return u;
}

template<int EPI>
__global__ __launch_bounds__(256, 2) void gemm_tc(
    const float* __restrict__ A, const float* __restrict__ B,
    const float* __restrict__ bias, float* __restrict__ C,
    int N, int K) {
    // As stored [m][k] (stride 20 -> conflict-free frag loads)
    // Bs stored [k][n] (stride 132 -> 16B-aligned float4 stores, conflict-free frag loads)
    __shared__ uint32_t As[128][20];
    __shared__ uint32_t Bs[16][132];

    const int t    = threadIdx.x;
    const int warp = t >> 5, lane = t & 31;
    const int wm   = warp >> 2, wn = warp & 3;      // 2 x 4 warp grid
    const int g    = lane >> 2, tig = lane & 3;     // groupID, threadID-in-group
    const int bm   = blockIdx.y * 128;
    const int bn   = blockIdx.x * 128;

    const float* Abase = A + (size_t)bm * K;
    const float* Bbase = B + bn;

    // global-load geometry (float4 per thread, x2)
    const int rA = t >> 2, kA = (t & 3) << 2;       // A: rows rA, rA+64; cols kA..kA+3
    const int rB = t >> 5, cB = (t & 31) << 2;      // B: rows rB, rB+8;  cols cB..cB+3

    float acc[4][4][4];
    #pragma unroll
    for (int i = 0; i < 4; i++)
        #pragma unroll
        for (int j = 0; j < 4; j++)
            #pragma unroll
            for (int r = 0; r < 4; r++) acc[i][j][r] = 0.f;

    float4 ra0, ra1, rb0, rb1;
    // prologue fetch
    ra0 = *(const float4*)(Abase + (size_t)rA       * K + kA);
    ra1 = *(const float4*)(Abase + (size_t)(rA + 64) * K + kA);
    rb0 = *(const float4*)(Bbase + (size_t)rB       * N + cB);
    rb1 = *(const float4*)(Bbase + (size_t)(rB + 8) * N + cB);

    #define STORE_SMEM() do {                                                   \
        uint4 w;                                                                \
        w.x=tf32cvt(ra0.x); w.y=tf32cvt(ra0.y); w.z=tf32cvt(ra0.z); w.w=tf32cvt(ra0.w); \
        *(uint4*)&As[rA][kA] = w;                                               \
        w.x=tf32cvt(ra1.x); w.y=tf32cvt(ra1.y); w.z=tf32cvt(ra1.z); w.w=tf32cvt(ra1.w); \
        *(uint4*)&As[rA+64][kA] = w;                                            \
        w.x=tf32cvt(rb0.x); w.y=tf32cvt(rb0.y); w.z=tf32cvt(rb0.z); w.w=tf32cvt(rb0.w); \
        *(uint4*)&Bs[rB][cB] = w;                                               \
        w.x=tf32cvt(rb1.x); w.y=tf32cvt(rb1.y); w.z=tf32cvt(rb1.z); w.w=tf32cvt(rb1.w); \
        *(uint4*)&Bs[rB+8][cB] = w;                                             \
    } while (0)

    STORE_SMEM();
    __syncthreads();

    for (int k0 = 16; k0 <= K; k0 += 16) {
        if (k0 < K) {  // prefetch next K-tile into registers
            ra0 = *(const float4*)(Abase + (size_t)rA       * K + k0 + kA);
            ra1 = *(const float4*)(Abase + (size_t)(rA + 64) * K + k0 + kA);
            rb0 = *(const float4*)(Bbase + (size_t)(k0 + rB)     * N + cB);
            rb1 = *(const float4*)(Bbase + (size_t)(k0 + rB + 8) * N + cB);
        }
        // two k-steps of 8
        #pragma unroll
        for (int ks = 0; ks < 2; ks++) {
            const int k8 = ks * 8;
            uint32_t a[4][4];
            #pragma unroll
            for (int mt = 0; mt < 4; mt++) {
                int m = wm * 64 + mt * 16 + g;
                a[mt][0] = As[m    ][k8 + tig];
                a[mt][1] = As[m + 8][k8 + tig];
                a[mt][2] = As[m    ][k8 + tig + 4];
                a[mt][3] = As[m + 8][k8 + tig + 4];
            }
            #pragma unroll
            for (int nt = 0; nt < 4; nt++) {
                int n = wn * 32 + nt * 8 + g;
                uint32_t b0 = Bs[k8 + tig    ][n];
                uint32_t b1 = Bs[k8 + tig + 4][n];
                #pragma unroll
                for (int mt = 0; mt < 4; mt++) {
                    asm volatile(
                        "mma.sync.aligned.m16n8k8.row.col.f32.tf32.tf32.f32 "
                        "{%0,%1,%2,%3}, {%4,%5,%6,%7}, {%8,%9}, {%0,%1,%2,%3};\n"
                        : "+f"(acc[mt][nt][0]), "+f"(acc[mt][nt][1]),
                          "+f"(acc[mt][nt][2]), "+f"(acc[mt][nt][3])
                        : "r"(a[mt][0]), "r"(a[mt][1]), "r"(a[mt][2]), "r"(a[mt][3]),
                          "r"(b0), "r"(b1));
                }
            }
        }
        __syncthreads();
        if (k0 < K) {
            STORE_SMEM();
            __syncthreads();
        }
    }
    #undef STORE_SMEM

    // epilogue: c0 at (row g, col 2*tig), c1 +1 col, c2/c3 at row+8
    #pragma unroll
    for (int nt = 0; nt < 4; nt++) {
        int n = bn + wn * 32 + nt * 8 + 2 * tig;
        float2 bv = *(const float2*)(bias + n);
        #pragma unroll
        for (int mt = 0; mt < 4; mt++) {
            int r = bm + wm * 64 + mt * 16 + g;
            float2 o0 = make_float2(acc[mt][nt][0] + bv.x, acc[mt][nt][1] + bv.y);
            float2 o1 = make_float2(acc[mt][nt][2] + bv.x, acc[mt][nt][3] + bv.y);
            if (EPI == 1) {
                o0.x = gelu_exact(o0.x); o0.y = gelu_exact(o0.y);
                o1.x = gelu_exact(o1.x); o1.y = gelu_exact(o1.y);
            }
            *(float2*)(C + (size_t)r * N + n)       = o0;
            *(float2*)(C + (size_t)(r + 8) * N + n) = o1;
        }
    }
}

// =================== fused causal attention (flash-style, fp32) ===================
#define ATTN_SMEM (4*64*65*4)

__global__ __launch_bounds__(256) void attn_kernel(const float* __restrict__ qkv,
                                                   float* __restrict__ out) {
    extern __shared__ float sm[];
    float (*Qs)[65] = (float(*)[65])(sm);
    float (*Ks)[65] = (float(*)[65])(sm + 64*65);
    float (*Vs)[65] = (float(*)[65])(sm + 2*64*65);
    float (*Ps)[65] = (float(*)[65])(sm + 3*64*65);
    const int qt = blockIdx.x, h = blockIdx.y, b = blockIdx.z;
    const int t  = threadIdx.x;
    const int qi = t >> 2, g = t & 3;

    const int RS = 3*DIM;
    const float* qbase = qkv + (size_t)(b*SEQ) * RS + h * (3*HD);

    #pragma unroll
    for (int i = 0; i < 4; i++) {
        int f = t + i*256;
        int r = f >> 4;
        int c = (f & 15) << 2;
        float4 v = *(const float4*)(qbase + (size_t)(qt*64 + r) * RS + c);
        Qs[r][c]=v.x; Qs[r][c+1]=v.y; Qs[r][c+2]=v.z; Qs[r][c+3]=v.w;
    }

    float m = -INFINITY, l = 0.f;
    float o[16];
    #pragma unroll
    for (int i = 0; i < 16; i++) o[i] = 0.f;
    const int qg = qt*64 + qi;

    for (int kt = 0; kt <= qt; kt++) {
        __syncthreads();
        #pragma unroll
        for (int i = 0; i < 4; i++) {
            int f = t + i*256;
            int r = f >> 4;
            int c = (f & 15) << 2;
            const float* base = qbase + (size_t)(kt*64 + r) * RS + 64 + c;
            float4 kv = *(const float4*)(base);
            Ks[r][c]=kv.x; Ks[r][c+1]=kv.y; Ks[r][c+2]=kv.z; Ks[r][c+3]=kv.w;
            float4 vv = *(const float4*)(base + 64);
            Vs[r][c]=vv.x; Vs[r][c+1]=vv.y; Vs[r][c+2]=vv.z; Vs[r][c+3]=vv.w;
        }
        __syncthreads();

        float sreg[16];
        #pragma unroll
        for (int j = 0; j < 16; j++) sreg[j] = 0.f;
        #pragma unroll
        for (int d0 = 0; d0 < 64; d0 += 16) {
            float q[16];
            #pragma unroll
            for (int dd = 0; dd < 16; dd++) q[dd] = Qs[qi][d0+dd];
            #pragma unroll
            for (int j = 0; j < 16; j++) {
                const float* kr = &Ks[j*4 + g][d0];
                #pragma unroll
                for (int dd = 0; dd < 16; dd++) sreg[j] += q[dd] * kr[dd];
            }
        }
        float tmax = -INFINITY;
        #pragma unroll
        for (int j = 0; j < 16; j++) {
            int kgl = kt*64 + j*4 + g;
            float sv = sreg[j] * 0.125f;
            if (kgl > qg) sv = -INFINITY;
            sreg[j] = sv;
            tmax = fmaxf(tmax, sv);
        }
        tmax = fmaxf(tmax, __shfl_xor_sync(0xffffffffu, tmax, 1));
        tmax = fmaxf(tmax, __shfl_xor_sync(0xffffffffu, tmax, 2));
        float nm   = fmaxf(m, tmax);
        float corr = expf(m - nm);
        m = nm;

        float lsum = 0.f;
        #pragma unroll
        for (int j = 0; j < 16; j++) {
            float p = expf(sreg[j] - m);
            lsum += p;
            Ps[qi][j*4 + g] = p;
        }
        lsum += __shfl_xor_sync(0xffffffffu, lsum, 1);
        lsum += __shfl_xor_sync(0xffffffffu, lsum, 2);
        l = l * corr + lsum;
        #pragma unroll
        for (int c = 0; c < 16; c++) o[c] *= corr;
        __syncwarp();

        for (int kj = 0; kj < 64; kj++) {
            float p = Ps[qi][kj];
            const float* vr = &Vs[kj][0];
            #pragma unroll
            for (int c = 0; c < 16; c++)
                o[c] += p * vr[c*4 + g];
        }
    }

    float inv = 1.f / l;
    float* orow = out + (size_t)(b*SEQ + qg) * DIM + h * HD;
    #pragma unroll
    for (int c = 0; c < 16; c++)
        orow[c*4 + g] = o[c] * inv;
}

// =================== residual add + LayerNorm ===================
__global__ __launch_bounds__(256) void add_ln_kernel(
    const float* __restrict__ x, const float* __restrict__ a,
    const float* __restrict__ scale, const float* __restrict__ bias,
    float* __restrict__ out, int has_a) {
    int row = blockIdx.x;
    const float* xr = x + (size_t)row * DIM;
    const float* ar = a + (size_t)row * DIM;
    int t = threadIdx.x;
    float v[4];
    float s = 0.f, s2 = 0.f;
    #pragma unroll
    for (int i = 0; i < 4; i++) {
        int d = t + i*256;
        float val = xr[d] + (has_a ? ar[d] : 0.f);
        v[i] = val; s += val; s2 += val*val;
    }
    __shared__ float red[2][8];
    #pragma unroll
    for (int off = 16; off; off >>= 1) {
        s  += __shfl_xor_sync(0xffffffffu, s,  off);
        s2 += __shfl_xor_sync(0xffffffffu, s2, off);
    }
    if ((t & 31) == 0) { red[0][t>>5] = s; red[1][t>>5] = s2; }
    __syncthreads();
    float ts = 0.f, ts2 = 0.f;
    #pragma unroll
    for (int i = 0; i < 8; i++) { ts += red[0][i]; ts2 += red[1][i]; }
    float mean = ts * (1.0f/DIM);
    float var  = ts2 * (1.0f/DIM) - mean*mean;
    float inv  = rsqrtf(var + 1e-5f);
    float* orow = out + (size_t)row * DIM;
    #pragma unroll
    for (int i = 0; i < 4; i++) {
        int d = t + i*256;
        orow[d] = (v[i] - mean) * inv * scale[d] + bias[d];
    }
}

// =================== final row softmax over VOCAB (in place) ===================
__global__ __launch_bounds__(256) void softmax_kernel(float* __restrict__ out) {
    int row = blockIdx.x;
    float* r = out + (size_t)row * VOCAB;
    int t = threadIdx.x;
    float mx = -INFINITY;
    for (int i = t; i < VOCAB; i += 256) mx = fmaxf(mx, r[i]);
    __shared__ float redm[8], reds[8];
    #pragma unroll
    for (int off = 16; off; off >>= 1) mx = fmaxf(mx, __shfl_xor_sync(0xffffffffu, mx, off));
    if ((t & 31) == 0) redm[t>>5] = mx;
    __syncthreads();
    float bm = -INFINITY;
    #pragma unroll
    for (int i = 0; i < 8; i++) bm = fmaxf(bm, redm[i]);
    float sum = 0.f;
    for (int i = t; i < VOCAB; i += 256) {
        float e = expf(r[i] - bm);
        r[i] = e; sum += e;
    }
    #pragma unroll
    for (int off = 16; off; off >>= 1) sum += __shfl_xor_sync(0xffffffffu, sum, off);
    if ((t & 31) == 0) reds[t>>5] = sum;
    __syncthreads();
    float bs = 0.f;
    #pragma unroll
    for (int i = 0; i < 8; i++) bs += reds[i];
    float inv = 1.f / bs;
    for (int i = t; i < VOCAB; i += 256) r[i] *= inv;
}

// =================== launch ===================
extern "C" void kernel_launch(void* const* d_in, const int* in_sizes, int n_in,
                              void* d_out, int out_size) {
    const int*   X      = (const int*)  d_in[0];
    const float* tok    = (const float*)d_in[1];
    const float* pos    = (const float*)d_in[2];
    const float* qkv_w  = (const float*)d_in[3];
    const float* qkv_b  = (const float*)d_in[4];
    const float* out_w  = (const float*)d_in[5];
    const float* out_b  = (const float*)d_in[6];
    const float* ln1_s  = (const float*)d_in[7];
    const float* ln1_b  = (const float*)d_in[8];
    const float* ln2_s  = (const float*)d_in[9];
    const float* ln2_b  = (const float*)d_in[10];
    const float* ff1_w  = (const float*)d_in[11];
    const float* ff1_b  = (const float*)d_in[12];
    const float* ff2_w  = (const float*)d_in[13];
    const float* ff2_b  = (const float*)d_in[14];
    const float* lnf_s  = (const float*)d_in[15];
    const float* lnf_b  = (const float*)d_in[16];
    const float* head_w = (const float*)d_in[17];
    const float* head_b = (const float*)d_in[18];
    float* outp = (float*)d_out;

    float *x, *qkvb, *ao, *ff, *tmp;
    cudaGetSymbolAddress((void**)&x,    g_x);
    cudaGetSymbolAddress((void**)&qkvb, g_qkv);
    cudaGetSymbolAddress((void**)&ao,   g_ao);
    cudaGetSymbolAddress((void**)&ff,   g_ff);
    cudaGetSymbolAddress((void**)&tmp,  g_t);

    cudaFuncSetAttribute(attn_kernel, cudaFuncAttributeMaxDynamicSharedMemorySize, ATTN_SMEM);

    embed_kernel<<<ROWS, 256>>>(X, tok, pos, x);

    for (int l = 0; l < LAYERS; l++) {
        gemm_tc<0><<<dim3(3*DIM/128, ROWS/128), 256>>>(x, qkv_w, qkv_b, qkvb, 3*DIM, DIM);
        attn_kernel<<<dim3(SEQ/64, NH, BATCH), 256, ATTN_SMEM>>>(qkvb, ao);
        gemm_tc<0><<<dim3(DIM/128, ROWS/128), 256>>>(ao, out_w, out_b, tmp, DIM, DIM);
        add_ln_kernel<<<ROWS, 256>>>(x, tmp, ln1_s, ln1_b, x, 1);
        gemm_tc<1><<<dim3(FFD/128, ROWS/128), 256>>>(x, ff1_w, ff1_b, ff, FFD, DIM);
        gemm_tc<0><<<dim3(DIM/128, ROWS/128), 256>>>(ff, ff2_w, ff2_b, tmp, DIM, FFD);
        add_ln_kernel<<<ROWS, 256>>>(x, tmp, ln2_s, ln2_b, x, 1);
    }
    add_ln_kernel<<<ROWS, 256>>>(x, x, lnf_s, lnf_b, x, 0);
    gemm_tc<0><<<dim3(VOCAB/128, ROWS/128), 256>>>(x, head_w, head_b, outp, VOCAB, DIM);
    softmax_kernel<<<ROWS, 256>>>(outp);
}